// round 2
// baseline (speedup 1.0000x reference)
#include <cuda_runtime.h>

// Problem constants (fixed by setup_inputs)
#define U_N 60000
#define I_N 30000
#define E_D 64
#define T_N 2000
#define N_N (U_N + I_N)
#define NLAYERS 3

// Scratch (device globals — no allocation allowed)
__device__ float g_bufA[(size_t)N_N * E_D];
__device__ float g_bufB[(size_t)N_N * E_D];
__device__ float g_hA[(size_t)I_N * E_D];
__device__ float g_hB[(size_t)I_N * E_D];
__device__ float g_ytag[(size_t)T_N * E_D];
__device__ float g_Bdeg[T_N];
__device__ float g_Binv[T_N];
__device__ float g_Ddeg[I_N];
__device__ float g_Dinv[I_N];

// Vector f32x4 global reduction (sm_90+): one RED.128 instead of 4 scalar atomics.
__device__ __forceinline__ void red_add_v4(float* addr, float4 v) {
    asm volatile("red.global.add.v4.f32 [%0], {%1, %2, %3, %4};"
                 :: "l"(addr), "f"(v.x), "f"(v.y), "f"(v.z), "f"(v.w)
                 : "memory");
}

__global__ void k_zero4(float4* __restrict__ p, int n4) {
    int i = blockIdx.x * blockDim.x + threadIdx.x;
    if (i < n4) p[i] = make_float4(0.f, 0.f, 0.f, 0.f);
}

// cur = acc = concat(user_embeds, item_embeds)
__global__ void k_init(const float* __restrict__ ue, const float* __restrict__ ie,
                       float* __restrict__ acc, float* __restrict__ cur) {
    int i = blockIdx.x * blockDim.x + threadIdx.x;
    if (i >= N_N * E_D) return;
    float v = (i < U_N * E_D) ? ue[i] : ie[i - U_N * E_D];
    acc[i] = v;
    cur[i] = v;
}

__global__ void k_deg(const int* __restrict__ items, const int* __restrict__ tags, int nh) {
    int i = blockIdx.x * blockDim.x + threadIdx.x;
    if (i >= nh) return;
    atomicAdd(&g_Bdeg[tags[i]], 1.f);
    atomicAdd(&g_Ddeg[items[i]], 1.f);
}

__global__ void k_inv() {
    int i = blockIdx.x * blockDim.x + threadIdx.x;
    if (i < T_N) { float b = g_Bdeg[i]; g_Binv[i] = 1.f / (b == 0.f ? 1.f : b); }
    if (i < I_N) { float d = g_Ddeg[i]; g_Dinv[i] = 1.f / (d == 0.f ? 1.f : d); }
}

// Edge-parallel COO SpMM: 16 threads per edge, one float4 chunk per thread.
__global__ void k_spmm(const int* __restrict__ rows, const int* __restrict__ cols,
                       const float* __restrict__ vals, const float* __restrict__ x,
                       float* __restrict__ y, int nnz) {
    long long t = (long long)blockIdx.x * blockDim.x + threadIdx.x;
    int e = (int)(t >> 4);
    if (e >= nnz) return;
    int c = (int)(t & 15);
    int r  = rows[e];
    int cc = cols[e];
    float v = vals[e];
    float4 xv = *(const float4*)(x + (size_t)cc * E_D + c * 4);
    red_add_v4(y + (size_t)r * E_D + c * 4,
               make_float4(v * xv.x, v * xv.y, v * xv.z, v * xv.w));
}

__global__ void k_acc_add(float4* __restrict__ acc, const float4* __restrict__ src, int n4) {
    int i = blockIdx.x * blockDim.x + threadIdx.x;
    if (i >= n4) return;
    float4 a = acc[i], s = src[i];
    acc[i] = make_float4(a.x + s.x, a.y + s.y, a.z + s.z, a.w + s.w);
}

__global__ void k_copy(const float4* __restrict__ s, float4* __restrict__ d, int n4) {
    int i = blockIdx.x * blockDim.x + threadIdx.x;
    if (i < n4) d[i] = s[i];
}

__global__ void k_copy2(const float4* __restrict__ s, float4* __restrict__ d1,
                        float4* __restrict__ d2, int n4) {
    int i = blockIdx.x * blockDim.x + threadIdx.x;
    if (i >= n4) return;
    float4 v = s[i];
    d1[i] = v;
    d2[i] = v;
}

// ytag[tag] += x[item]   (hypergraph H^T x)
__global__ void k_hconv1(const int* __restrict__ items, const int* __restrict__ tags,
                         const float* __restrict__ x, int nh) {
    long long t = (long long)blockIdx.x * blockDim.x + threadIdx.x;
    int e = (int)(t >> 4);
    if (e >= nh) return;
    int c = (int)(t & 15);
    int it = items[e];
    int tg = tags[e];
    float4 xv = *(const float4*)(x + (size_t)it * E_D + c * 4);
    red_add_v4(g_ytag + (size_t)tg * E_D + c * 4, xv);
}

// dst[item] += B_inv[tag] * ytag[tag]   (H B^-1 y)
__global__ void k_hconv2(const int* __restrict__ items, const int* __restrict__ tags,
                         float* __restrict__ dst, int nh) {
    long long t = (long long)blockIdx.x * blockDim.x + threadIdx.x;
    int e = (int)(t >> 4);
    if (e >= nh) return;
    int c = (int)(t & 15);
    int it = items[e];
    int tg = tags[e];
    float bi = g_Binv[tg];
    float4 yv = *(const float4*)(g_ytag + (size_t)tg * E_D + c * 4);
    red_add_v4(dst + (size_t)it * E_D + c * 4,
               make_float4(bi * yv.x, bi * yv.y, bi * yv.z, bi * yv.w));
}

// hcur = raw * D_inv (next-layer input, in place) ; hacc += hcur
__global__ void k_hfinal(const float* __restrict__ raw, float* __restrict__ hcur,
                         float* __restrict__ hacc, int n) {
    int i = blockIdx.x * blockDim.x + threadIdx.x;
    if (i >= n) return;
    float v = raw[i] * g_Dinv[i >> 6];
    hcur[i] = v;
    hacc[i] += v;
}

static inline int cdiv_ll(long long a, long long b) { return (int)((a + b - 1) / b); }

extern "C" void kernel_launch(void* const* d_in, const int* in_sizes, int n_in,
                              void* d_out, int out_size) {
    const float* ue      = (const float*)d_in[0];
    const float* ie      = (const float*)d_in[1];
    const float* hgu     = (const float*)d_in[2];
    const float* hgi     = (const float*)d_in[3];
    const int*   adj_r   = (const int*)d_in[4];
    const int*   adj_c   = (const int*)d_in[5];
    const float* adj_v   = (const float*)d_in[6];
    const int*   h_items = (const int*)d_in[7];
    const int*   h_tags  = (const int*)d_in[8];
    const int*   ui_r    = (const int*)d_in[9];
    const int*   ui_c    = (const int*)d_in[10];
    const float* ui_v    = (const float*)d_in[11];
    const int n_adj = in_sizes[4];
    const int nh    = in_sizes[7];
    const int nui   = in_sizes[9];
    // layer_num is always 3 (setup_inputs); host-side loop count must be static anyway.

    float* acc     = (float*)d_out;                       // [N_N, E_D]
    float* hg_user = acc + (size_t)N_N * E_D;             // [U_N, E_D]
    float* hacc    = hg_user + (size_t)U_N * E_D;         // [I_N, E_D]

    float *bufA, *bufB, *hA, *hB, *ytag, *Bdeg, *Ddeg;
    cudaGetSymbolAddress((void**)&bufA, g_bufA);
    cudaGetSymbolAddress((void**)&bufB, g_bufB);
    cudaGetSymbolAddress((void**)&hA,   g_hA);
    cudaGetSymbolAddress((void**)&hB,   g_hB);
    cudaGetSymbolAddress((void**)&ytag, g_ytag);
    cudaGetSymbolAddress((void**)&Bdeg, g_Bdeg);
    cudaGetSymbolAddress((void**)&Ddeg, g_Ddeg);

    const int TB = 256;
    const int NE  = N_N * E_D;   // 5,760,000
    const int IE  = I_N * E_D;   // 1,920,000
    const int UE  = U_N * E_D;   // 3,840,000
    const int TE  = T_N * E_D;   // 128,000

    // ---- init: cur = acc = concat(ue, ie) ----
    k_init<<<cdiv_ll(NE, TB), TB>>>(ue, ie, acc, bufA);

    // ---- hypergraph degrees ----
    k_zero4<<<cdiv_ll(T_N / 4, TB), TB>>>((float4*)Bdeg, T_N / 4);
    k_zero4<<<cdiv_ll(I_N / 4, TB), TB>>>((float4*)Ddeg, I_N / 4);
    k_deg<<<cdiv_ll(nh, TB), TB>>>(h_items, h_tags, nh);
    k_inv<<<cdiv_ll(I_N, TB), TB>>>();

    // ---- LightGCN: 3 layers of adjacency SpMM, acc += layer output ----
    float* src = bufA;
    float* dst = bufB;
    for (int l = 0; l < NLAYERS; l++) {
        k_zero4<<<cdiv_ll(NE / 4, TB), TB>>>((float4*)dst, NE / 4);
        k_spmm<<<cdiv_ll(16LL * n_adj, TB), TB>>>(adj_r, adj_c, adj_v, src, dst, n_adj);
        k_acc_add<<<cdiv_ll(NE / 4, TB), TB>>>((float4*)acc, (const float4*)dst, NE / 4);
        float* tmp = src; src = dst; dst = tmp;
    }

    // ---- hypergraph propagation on items: 3 layers ----
    k_copy2<<<cdiv_ll(IE / 4, TB), TB>>>((const float4*)hgi, (float4*)hA, (float4*)hacc, IE / 4);
    for (int l = 0; l < NLAYERS; l++) {
        k_zero4<<<cdiv_ll(TE / 4, TB), TB>>>((float4*)ytag, TE / 4);
        k_zero4<<<cdiv_ll(IE / 4, TB), TB>>>((float4*)hB, IE / 4);
        k_hconv1<<<cdiv_ll(16LL * nh, TB), TB>>>(h_items, h_tags, hA, nh);
        k_hconv2<<<cdiv_ll(16LL * nh, TB), TB>>>(h_items, h_tags, hB, nh);
        // hA := hB * D_inv (next layer input), hacc += same
        k_hfinal<<<cdiv_ll(IE, TB), TB>>>(hB, hA, hacc, IE);
    }

    // ---- hypergraph user embeds: hg_user = hgu + ui_spmm(hacc) ----
    k_copy<<<cdiv_ll(UE / 4, TB), TB>>>((const float4*)hgu, (float4*)hg_user, UE / 4);
    k_spmm<<<cdiv_ll(16LL * nui, TB), TB>>>(ui_r, ui_c, ui_v, hacc, hg_user, nui);
}